// round 14
// baseline (speedup 1.0000x reference)
#include <cuda_runtime.h>
#include <cuda_fp16.h>
#include <cstdint>
#include <math.h>

#define B_ 4
#define T_ 2048
#define C_ 1024
#define H_ 16
#define D_ 64
#define R_ 64
#define NT 8192   // B*T

// ---------------- scratch (device globals; no allocation) ----------------
__device__ __half g_xh[NT * C_];      // x converted to half
__device__ __half g_W[256 * 1024];    // stacked scaled V-weights (half)
__device__ __half g_Wu[4 * 1024 * 64];// U weights (half)
__device__ __half g_P[NT * 192];      // rank-space P for q,k,v
__device__ __half g_P2[NT * 64];      // rank-space P for c-proj
__device__ __half g_Qh[NT * C_];      // [B,H,T,D], pre-scaled by 0.125*log2e
__device__ __half g_Kh[NT * C_];
__device__ __half g_Vh[NT * C_];
__device__ __half g_Yh[NT * C_];      // attention out [B,T,C]

// =================== portable tensor-core helpers (sm_80+) =================
__device__ __forceinline__ void mma_f16(float* d, const uint32_t* a,
                                        uint32_t b0, uint32_t b1) {
    asm volatile(
        "mma.sync.aligned.m16n8k16.row.col.f32.f16.f16.f32 "
        "{%0,%1,%2,%3}, {%4,%5,%6,%7}, {%8,%9}, {%0,%1,%2,%3};"
        : "+f"(d[0]), "+f"(d[1]), "+f"(d[2]), "+f"(d[3])
        : "r"(a[0]), "r"(a[1]), "r"(a[2]), "r"(a[3]), "r"(b0), "r"(b1));
}
__device__ __forceinline__ uint32_t smem_u32(const void* p) {
    uint32_t a;
    asm("{ .reg .u64 t; cvta.to.shared.u64 t, %1; cvt.u32.u64 %0, t; }"
        : "=r"(a) : "l"(p));
    return a;
}
__device__ __forceinline__ void cp16(uint32_t dst, const void* src) {
    asm volatile("cp.async.cg.shared.global [%0], [%1], 16;"
                 :: "r"(dst), "l"(src));
}
#define CP_COMMIT() asm volatile("cp.async.commit_group;" ::: "memory")
#define CP_WAIT(n)  asm volatile("cp.async.wait_group %0;" :: "n"(n) : "memory")
#define LDSM4(r, a)                                                         \
    asm volatile("ldmatrix.sync.aligned.m8n8.x4.shared.b16 "                \
                 "{%0,%1,%2,%3}, [%4];"                                     \
                 : "=r"((r)[0]), "=r"((r)[1]), "=r"((r)[2]), "=r"((r)[3])   \
                 : "r"(a))
#define LDSM4T(r, a)                                                        \
    asm volatile("ldmatrix.sync.aligned.m8n8.x4.trans.shared.b16 "          \
                 "{%0,%1,%2,%3}, [%4];"                                     \
                 : "=r"((r)[0]), "=r"((r)[1]), "=r"((r)[2]), "=r"((r)[3])   \
                 : "r"(a))
__device__ __forceinline__ uint32_t pack_h2(float lo, float hi) {
    __half2 h = __floats2half2_rn(lo, hi);
    return *(uint32_t*)&h;
}
__device__ __forceinline__ uint32_t h2exp2(uint32_t u) {
    uint32_t r;
    asm("ex2.approx.f16x2 %0, %1;" : "=r"(r) : "r"(u));
    return r;
}

// ---------------------------------------------------------------------------
// K_prep: blocks [0,2048): x fp32 -> half
//         blocks [2048,2304): scaled V-weights -> g_W
//         blocks [2304,2560): U weights -> g_Wu
// ---------------------------------------------------------------------------
__global__ __launch_bounds__(256) void k_prep(
    const float* __restrict__ x,
    const float* __restrict__ qU, const float* __restrict__ kU,
    const float* __restrict__ vU, const float* __restrict__ cU,
    const float* __restrict__ qV, const float* __restrict__ kV,
    const float* __restrict__ vV, const float* __restrict__ cV) {
    const int b = blockIdx.x, tid = threadIdx.x;
    if (b < 2048) {
        const int base = (b * 256 + tid) * 16;
        #pragma unroll
        for (int g = 0; g < 4; g++) {
            float4 v = *(const float4*)(x + base + g * 4);
            *(__half2*)(g_xh + base + g * 4)     = __floats2half2_rn(v.x, v.y);
            *(__half2*)(g_xh + base + g * 4 + 2) = __floats2half2_rn(v.z, v.w);
        }
    } else if (b < 2304) {
        const int bb = b - 2048;
        const int grp = bb >> 6, r = bb & 63;
        const float* Vsrc = (grp == 0) ? qV : (grp == 1) ? kV
                          : (grp == 2) ? vV : cV;
        float sc = powf((float)(r + 1), -0.7f);
        if (grp == 0) sc *= 0.125f * 1.4426950408889634f;
        const int c = tid * 4;
        float4 v = *(const float4*)(Vsrc + (size_t)r * 1024 + c);
        *(__half2*)(g_W + (size_t)bb * 1024 + c)     = __floats2half2_rn(v.x * sc, v.y * sc);
        *(__half2*)(g_W + (size_t)bb * 1024 + c + 2) = __floats2half2_rn(v.z * sc, v.w * sc);
    } else {
        const float* Us[4] = {qU, kU, vU, cU};
        const int base = (b - 2304) * 1024 + tid * 4;
        const int w = base >> 16, off = base & 65535;
        float4 u = *(const float4*)(Us[w] + off);
        *(__half2*)(g_Wu + base)     = __floats2half2_rn(u.x, u.y);
        *(__half2*)(g_Wu + base + 2) = __floats2half2_rn(u.z, u.w);
    }
}

// ---------------------------------------------------------------------------
// K1a: stage-1 qkv GEMM  P[m, n] = x[m,:1024] @ W[n,:1024]^T, NOUT=192.
// 128 threads/CTA, tile 32x192, grid 256. Warp: 32x48 = 12 chains.
// 3-stage cp.async pipeline, single __syncthreads per chunk.
// ---------------------------------------------------------------------------
#define PADH1 40   // halfs; 80B row stride
__global__ __launch_bounds__(128) void k_g1a(const __half* __restrict__ A,
                                             __half* __restrict__ Pout) {
    extern __shared__ __half sg1h[];
    const int tid = threadIdx.x, w = tid >> 5, lane = tid & 31;
    const int quad = lane >> 2, qc = lane & 3;
    const int m0 = blockIdx.x * 32;
    constexpr int STRIDE = (32 + 192) * PADH1;   // halfs per stage
    const uint32_t sb = smem_u32(sg1h);

    auto stage = [&](int ch, int s) {
        const int k0 = ch * 32;
        const uint32_t base = sb + s * STRIDE * 2;
        #pragma unroll
        for (int i = tid; i < (32 + 192) * 4; i += 128) {
            int row = i >> 2, c8 = (i & 3) * 8;
            const __half* src = (row < 32)
                ? A   + (size_t)(m0 + row) * 1024 + k0 + c8
                : g_W + (size_t)(row - 32) * 1024 + k0 + c8;
            cp16(base + (row * PADH1 + c8) * 2, src);
        }
    };

    float acc[2][6][4];
    #pragma unroll
    for (int mf = 0; mf < 2; mf++)
        #pragma unroll
        for (int nb = 0; nb < 6; nb++)
            #pragma unroll
            for (int i = 0; i < 4; i++) acc[mf][nb][i] = 0.f;

    stage(0, 0); CP_COMMIT();
    stage(1, 1); CP_COMMIT();

    for (int ch = 0; ch < 32; ch++) {
        CP_WAIT(1);
        __syncthreads();
        if (ch + 2 < 32) stage(ch + 2, (ch + 2) % 3);
        CP_COMMIT();                      // unconditional (may be empty)
        const __half* Ab = sg1h + (ch % 3) * STRIDE;
        const __half* Bb = Ab + 32 * PADH1;
        #pragma unroll
        for (int kb = 0; kb < 2; kb++) {
            uint32_t a[2][4];
            #pragma unroll
            for (int mf = 0; mf < 2; mf++) {
                const __half* ap = Ab + (mf * 16 + quad) * PADH1
                                 + kb * 16 + 2 * qc;
                a[mf][0] = *(const uint32_t*)(ap);
                a[mf][1] = *(const uint32_t*)(ap + 8 * PADH1);
                a[mf][2] = *(const uint32_t*)(ap + 8);
                a[mf][3] = *(const uint32_t*)(ap + 8 * PADH1 + 8);
            }
            #pragma unroll
            for (int nb = 0; nb < 6; nb++) {
                const __half* bp = Bb + (w * 48 + nb * 8 + quad) * PADH1
                                 + kb * 16 + 2 * qc;
                uint32_t b0 = *(const uint32_t*)(bp);
                uint32_t b1 = *(const uint32_t*)(bp + 8);
                mma_f16(acc[0][nb], a[0], b0, b1);
                mma_f16(acc[1][nb], a[1], b0, b1);
            }
        }
    }

    #pragma unroll
    for (int mf = 0; mf < 2; mf++) {
        const int row = m0 + mf * 16 + quad;
        #pragma unroll
        for (int nb = 0; nb < 6; nb++) {
            const int col = w * 48 + nb * 8 + 2 * qc;
            *(__half2*)(Pout + (size_t)row * 192 + col) =
                __floats2half2_rn(acc[mf][nb][0], acc[mf][nb][1]);
            *(__half2*)(Pout + (size_t)(row + 8) * 192 + col) =
                __floats2half2_rn(acc[mf][nb][2], acc[mf][nb][3]);
        }
    }
}

// ---------------------------------------------------------------------------
// K1b: stage-1 c-proj GEMM  P2[m,n] = Y[m,:1024] @ W[192+n,:1024]^T, NOUT=64
// 256 threads, tile 64x64, 3-stage cp.async, single sync per chunk.
// ---------------------------------------------------------------------------
__global__ __launch_bounds__(256) void k_g1b(__half* __restrict__ Pout) {
    extern __shared__ __half sg1bh[];
    const int tid = threadIdx.x, w = tid >> 5, lane = tid & 31;
    const int quad = lane >> 2, qc = lane & 3;
    const int wm = w & 1, wn = w >> 1;
    const int m0 = blockIdx.x * 64;
    constexpr int STRIDE = 128 * PADH1;
    const __half* Wp = g_W + (size_t)192 * 1024;
    const uint32_t sb = smem_u32(sg1bh);

    auto stage = [&](int ch, int s) {
        const int k0 = ch * 32;
        const uint32_t base = sb + s * STRIDE * 2;
        #pragma unroll
        for (int i = tid; i < 128 * 4; i += 256) {
            int row = i >> 2, c8 = (i & 3) * 8;
            const __half* src = (row < 64)
                ? g_Yh + (size_t)(m0 + row) * 1024 + k0 + c8
                : Wp   + (size_t)(row - 64) * 1024 + k0 + c8;
            cp16(base + (row * PADH1 + c8) * 2, src);
        }
    };

    float acc[2][2][4] = {};
    stage(0, 0); CP_COMMIT();
    stage(1, 1); CP_COMMIT();

    for (int ch = 0; ch < 32; ch++) {
        CP_WAIT(1);
        __syncthreads();
        if (ch + 2 < 32) stage(ch + 2, (ch + 2) % 3);
        CP_COMMIT();                      // unconditional (may be empty)
        const __half* Ab = sg1bh + (ch % 3) * STRIDE;
        const __half* Bb = Ab + 64 * PADH1;
        #pragma unroll
        for (int kb = 0; kb < 2; kb++) {
            uint32_t a[2][4];
            #pragma unroll
            for (int mf = 0; mf < 2; mf++) {
                const __half* ap = Ab + (wm * 32 + mf * 16 + quad) * PADH1
                                 + kb * 16 + 2 * qc;
                a[mf][0] = *(const uint32_t*)(ap);
                a[mf][1] = *(const uint32_t*)(ap + 8 * PADH1);
                a[mf][2] = *(const uint32_t*)(ap + 8);
                a[mf][3] = *(const uint32_t*)(ap + 8 * PADH1 + 8);
            }
            #pragma unroll
            for (int nb = 0; nb < 2; nb++) {
                const __half* bp = Bb + (wn * 16 + nb * 8 + quad) * PADH1
                                 + kb * 16 + 2 * qc;
                uint32_t b0 = *(const uint32_t*)(bp);
                uint32_t b1 = *(const uint32_t*)(bp + 8);
                mma_f16(acc[0][nb], a[0], b0, b1);
                mma_f16(acc[1][nb], a[1], b0, b1);
            }
        }
    }

    #pragma unroll
    for (int mf = 0; mf < 2; mf++) {
        const int row = m0 + wm * 32 + mf * 16 + quad;
        #pragma unroll
        for (int nb = 0; nb < 2; nb++) {
            const int col = wn * 16 + nb * 8 + 2 * qc;
            *(__half2*)(Pout + (size_t)row * 64 + col) =
                __floats2half2_rn(acc[mf][nb][0], acc[mf][nb][1]);
            *(__half2*)(Pout + (size_t)(row + 8) * 64 + col) =
                __floats2half2_rn(acc[mf][nb][2], acc[mf][nb][3]);
        }
    }
}

// ---------------------------------------------------------------------------
// K2: stage-2 GEMM  y[m,n] = P[m,:64] @ U[n0+n,:64]^T   (non-persistent)
// M-tile 128 (8 warps x 16 rows), N-tile 128, K=64 single shot.
// ---------------------------------------------------------------------------
#define PADH2 72   // halfs; 144B row stride
__global__ __launch_bounds__(256) void k_g2(const __half* __restrict__ Pbase,
                                            int ps,
                                            const __half* __restrict__ Wubase,
                                            int mode, float* __restrict__ outp) {
    extern __shared__ __half sg2h[];
    __half* As = sg2h;                 // [128][PADH2]
    __half* Bs = sg2h + 128 * PADH2;   // [128][PADH2]
    const int tid = threadIdx.x, w = tid >> 5, lane = tid & 31;
    const int quad = lane >> 2, qc = lane & 3;
    const int m0 = blockIdx.y * 128, n0 = blockIdx.x * 128;
    const int z = blockIdx.z;
    const __half* Pin = Pbase + (mode == 0 ? z * 64 : 0);
    const __half* Wu  = Wubase + (mode == 0 ? z * 65536 : 0);
    const uint32_t sb = smem_u32(sg2h);

    #pragma unroll
    for (int t = 0; t < 4; t++) {       // A: 1024 cp16
        int idx = tid + t * 256;
        int r = idx >> 3, c8 = (idx & 7) * 8;
        cp16(sb + (r * PADH2 + c8) * 2, Pin + (size_t)(m0 + r) * ps + c8);
    }
    #pragma unroll
    for (int t = 0; t < 4; t++) {       // B: 1024 cp16
        int idx = tid + t * 256;
        int n = idx >> 3, c8 = (idx & 7) * 8;
        cp16(sb + (128 * PADH2 + n * PADH2 + c8) * 2,
             Wu + (size_t)(n0 + n) * 64 + c8);
    }
    CP_COMMIT();
    CP_WAIT(0);
    __syncthreads();

    float acc[16][4];
    #pragma unroll
    for (int nb = 0; nb < 16; nb++)
        #pragma unroll
        for (int i = 0; i < 4; i++) acc[nb][i] = 0.f;

    #pragma unroll
    for (int kb = 0; kb < 4; kb++) {
        uint32_t a[4];
        const __half* ap = As + (w * 16 + quad) * PADH2 + kb * 16 + 2 * qc;
        a[0] = *(const uint32_t*)(ap);
        a[1] = *(const uint32_t*)(ap + 8 * PADH2);
        a[2] = *(const uint32_t*)(ap + 8);
        a[3] = *(const uint32_t*)(ap + 8 * PADH2 + 8);
        #pragma unroll
        for (int nb = 0; nb < 16; nb++) {
            const __half* bp = Bs + (nb * 8 + quad) * PADH2 + kb * 16 + 2 * qc;
            mma_f16(acc[nb], a, *(const uint32_t*)(bp),
                    *(const uint32_t*)(bp + 8));
        }
    }

    const int row = m0 + w * 16 + quad;
    if (mode == 0) {
        __half* dst = (z == 0) ? g_Qh : (z == 1) ? g_Kh : g_Vh;
        const int b = row >> 11, t = row & (T_ - 1);
        #pragma unroll
        for (int nb = 0; nb < 16; nb++) {
            const int col = n0 + nb * 8 + 2 * qc;
            const int h = col >> 6, d = col & 63;
            __half* p0 = dst + (((size_t)(b * H_ + h) * T_ + t) * D_) + d;
            *(__half2*)p0 = __floats2half2_rn(acc[nb][0], acc[nb][1]);
            *(__half2*)(p0 + 8 * D_) = __floats2half2_rn(acc[nb][2], acc[nb][3]);
        }
    } else {
        #pragma unroll
        for (int nb = 0; nb < 16; nb++) {
            const int col = n0 + nb * 8 + 2 * qc;
            float* p0 = outp + (size_t)row * C_ + col;
            *(float2*)p0 = make_float2(acc[nb][0], acc[nb][1]);
            *(float2*)(p0 + 8 * C_) = make_float2(acc[nb][2], acc[nb][3]);
        }
    }
}

// ---------------------------------------------------------------------------
// K3: causal flash attention, fp16 mma + ldmatrix.
// 256 q-rows/CTA, 8 warps x 32 rows (mf=2): every K/V b-fragment feeds TWO
// m-fragments -> LDSM bytes per FLOP halved (smem crossbar was co-limiting).
// Pair-processed 64-key tiles, 4-deep buffers, one __syncthreads per pair.
// 1 CTA/SM (regs ~190, smem 110.6KB). exp via ex2.approx.f16x2; row-sums
// via constant ones b-fragment. Per-row arithmetic identical to R13.
// ---------------------------------------------------------------------------
#define PADA 72                   // halfs; 144B stride
#define KVB2 (64 * PADA * 2)      // bytes per single K or V tile buffer
__global__ __launch_bounds__(256, 1) void k_attn() {
    extern __shared__ __half sah[];
    const int tid = threadIdx.x, w = tid >> 5, lane = tid & 31;
    const int quad = lane >> 2, qc = lane & 3;
    const int msel = lane >> 3, rsel = lane & 7;
    const int mrow_a = (msel & 1) * 8 + rsel;   // Q / V(trans) row part
    const int mcol_a = (msel >> 1) * 8;
    const int mrow_b = (msel >> 1) * 8 + rsel;  // K row part
    const int mcol_b = (msel & 1) * 8;
    const int bh = blockIdx.y;
    const int qt = gridDim.x - 1 - blockIdx.x;  // heavy tiles first
    const int q0 = qt * 256;
    const __half* Qb = g_Qh + (size_t)bh * T_ * D_;
    const __half* Kb = g_Kh + (size_t)bh * T_ * D_;
    const __half* Vb = g_Vh + (size_t)bh * T_ * D_;
    const int nt = 4 * qt + 4;                  // even
    const int npair = 2 * qt + 2;
    const uint32_t vones = (quad == 0) ? 0x3C003C00u : 0u;  // half2 (1,1)

    // ---- precomputed SMEM addresses (bytes) ----
    const uint32_t SB = smem_u32(sah);
    const uint32_t QS = SB;                     // Qs [256][PADA]
    const uint32_t KS = SB + 256 * PADA * 2;    // Ksb[4][64][PADA]
    const uint32_t VS = KS + 4 * KVB2;          // Vsb[4][64][PADA]
    const uint32_t ka0 = KS + (mrow_b * PADA + mcol_b) * 2;
    const uint32_t va0 = VS + (mrow_a * PADA + mcol_a) * 2;
    // staging: thread covers rows r and r+32 at col c8
    const int r = tid >> 3, c8 = (tid & 7) * 8;
    const int gs0 = r * D_ + c8, gs1 = gs0 + 32 * D_;
    const uint32_t kst0 = KS + (r * PADA + c8) * 2;
    const uint32_t kst1 = kst0 + 32 * PADA * 2;
    const uint32_t vst0 = VS + (r * PADA + c8) * 2;
    const uint32_t vst1 = vst0 + 32 * PADA * 2;

    auto stage = [&](int j) {
        const __half* Kt = Kb + (size_t)j * 64 * D_;
        const __half* Vt = Vb + (size_t)j * 64 * D_;
        const uint32_t bo = (j & 3) * KVB2;
        cp16(kst0 + bo, Kt + gs0);
        cp16(kst1 + bo, Kt + gs1);
        cp16(vst0 + bo, Vt + gs0);
        cp16(vst1 + bo, Vt + gs1);
    };

    // Q tile (256 rows) + first pair, one commit group
    #pragma unroll
    for (int t = 0; t < 8; t++) {
        const int row = r + t * 32;
        cp16(QS + (row * PADA + c8) * 2, Qb + (size_t)(q0 + row) * D_ + c8);
    }
    stage(0);
    stage(1);
    CP_COMMIT();

    uint32_t qa[2][4][4];
    float o[2][8][4] = {};
    float oS[2][4] = {};    // ones-frag accumulators per mf

    auto compute = [&](int j, bool maskt) {
        const uint32_t kbase = ka0 + (j & 3) * KVB2;
        const uint32_t vbase = va0 + (j & 3) * KVB2;

        // S = Q @ K^T : 32x64 per warp; K b-frag shared across both mf
        float s[2][8][4];
        #pragma unroll
        for (int mf = 0; mf < 2; mf++)
            #pragma unroll
            for (int nb = 0; nb < 8; nb++)
                #pragma unroll
                for (int i = 0; i < 4; i++) s[mf][nb][i] = 0.f;
        #pragma unroll
        for (int kb = 0; kb < 4; kb++)
            #pragma unroll
            for (int nbp = 0; nbp < 4; nbp++) {
                uint32_t bf[4];
                LDSM4(bf, kbase + (nbp * 16 * PADA + kb * 16) * 2);
                #pragma unroll
                for (int mf = 0; mf < 2; mf++) {
                    mma_f16(s[mf][2 * nbp],     qa[mf][kb], bf[0], bf[1]);
                    mma_f16(s[mf][2 * nbp + 1], qa[mf][kb], bf[2], bf[3]);
                }
            }

        // causal mask (final 2 pairs only; literal bool -> DCE elsewhere)
        if (maskt) {
            #pragma unroll
            for (int mf = 0; mf < 2; mf++) {
                const int rowrel0 = q0 + w * 32 + mf * 16 + quad - 64 * j;
                #pragma unroll
                for (int nb = 0; nb < 8; nb++) {
                    const int k0 = nb * 8 + 2 * qc;
                    if (k0 > rowrel0)         s[mf][nb][0] = -1e30f;
                    if (k0 + 1 > rowrel0)     s[mf][nb][1] = -1e30f;
                    if (k0 > rowrel0 + 8)     s[mf][nb][2] = -1e30f;
                    if (k0 + 1 > rowrel0 + 8) s[mf][nb][3] = -1e30f;
                }
            }
        }

        // P = 2^S in f16x2; O += P @ V; Sum(p) += P @ ones
        #pragma unroll
        for (int kb = 0; kb < 4; kb++) {
            uint32_t pa[2][4];
            #pragma unroll
            for (int mf = 0; mf < 2; mf++) {
                pa[mf][0] = h2exp2(pack_h2(s[mf][2 * kb][0],     s[mf][2 * kb][1]));
                pa[mf][1] = h2exp2(pack_h2(s[mf][2 * kb][2],     s[mf][2 * kb][3]));
                pa[mf][2] = h2exp2(pack_h2(s[mf][2 * kb + 1][0], s[mf][2 * kb + 1][1]));
                pa[mf][3] = h2exp2(pack_h2(s[mf][2 * kb + 1][2], s[mf][2 * kb + 1][3]));
            }
            #pragma unroll
            for (int nbp = 0; nbp < 4; nbp++) {
                uint32_t vf[4];
                LDSM4T(vf, vbase + (kb * 16 * PADA + nbp * 16) * 2);
                #pragma unroll
                for (int mf = 0; mf < 2; mf++) {
                    mma_f16(o[mf][2 * nbp],     pa[mf], vf[0], vf[1]);
                    mma_f16(o[mf][2 * nbp + 1], pa[mf], vf[2], vf[3]);
                }
            }
            mma_f16(oS[0], pa[0], vones, vones);
            mma_f16(oS[1], pa[1], vones, vones);
        }
    };

    for (int p = 0; p < npair; p++) {
        CP_WAIT(0);
        __syncthreads();
        if (p == 0) {        // Q a-frags once (Q arrived with first group)
            #pragma unroll
            for (int mf = 0; mf < 2; mf++)
                #pragma unroll
                for (int kb = 0; kb < 4; kb++)
                    LDSM4(qa[mf][kb],
                          QS + ((w * 32 + mf * 16 + mrow_a) * PADA
                                + kb * 16 + mcol_a) * 2);
        }
        if (p + 1 < npair) {
            stage(2 * p + 2);
            stage(2 * p + 3);
            CP_COMMIT();
            const bool mk = (p >= npair - 3);   // 2nd-to-last pair: tiles may mask
            compute(2 * p,     mk && (2 * p     >= nt - 4));
            compute(2 * p + 1, mk && (2 * p + 1 >= nt - 4));
        } else {
            compute(2 * p,     true);
            compute(2 * p + 1, true);
        }
    }

    // ---- epilogue: Sum(p) at n=0 of oS frags (qc==0 lanes) ----
    const int b = bh >> 4, h = bh & 15;
    #pragma unroll
    for (int mf = 0; mf < 2; mf++) {
        const float l0 = __shfl_sync(0xffffffffu, oS[mf][0], lane & 28);
        const float l1 = __shfl_sync(0xffffffffu, oS[mf][2], lane & 28);
        const float inv0 = 1.f / l0, inv1 = 1.f / l1;
        const int r0 = q0 + w * 32 + mf * 16 + quad;
        __half* y0 = g_Yh + ((size_t)b * T_ + r0) * C_ + h * 64;
        __half* y1 = y0 + 8 * C_;
        #pragma unroll
        for (int nb = 0; nb < 8; nb++) {
            const int c = nb * 8 + 2 * qc;
            *(__half2*)(y0 + c) = __floats2half2_rn(o[mf][nb][0] * inv0,
                                                    o[mf][nb][1] * inv0);
            *(__half2*)(y1 + c) = __floats2half2_rn(o[mf][nb][2] * inv1,
                                                    o[mf][nb][3] * inv1);
        }
    }
}

// ---------------------------------------------------------------------------
extern "C" void kernel_launch(void* const* d_in, const int* in_sizes, int n_in,
                              void* d_out, int out_size) {
    (void)in_sizes; (void)n_in; (void)out_size;
    const float* x  = (const float*)d_in[0];
    const float* qU = (const float*)d_in[1];
    const float* qV = (const float*)d_in[2];
    const float* kU = (const float*)d_in[3];
    const float* kV = (const float*)d_in[4];
    const float* vU = (const float*)d_in[5];
    const float* vV = (const float*)d_in[6];
    const float* cU = (const float*)d_in[7];
    const float* cV = (const float*)d_in[8];
    float* out = (float*)d_out;

    const int sm_g1a = 3 * (32 + 192) * PADH1 * 2;              // 53760
    const int sm_g1b = 3 * 128 * PADH1 * 2;                     // 30720
    const int sm_g2  = 2 * 128 * PADH2 * 2;                     // 36864
    const int sm_att = (256 * PADA + 8 * 64 * PADA) * 2;        // 110592
    static int cfg_done = 0;
    if (!cfg_done) {
        cudaFuncSetAttribute(k_g1a,
            cudaFuncAttributeMaxDynamicSharedMemorySize, sm_g1a);
        cudaFuncSetAttribute(k_g1b,
            cudaFuncAttributeMaxDynamicSharedMemorySize, sm_g1b);
        cudaFuncSetAttribute(k_g2,
            cudaFuncAttributeMaxDynamicSharedMemorySize, sm_g2);
        cudaFuncSetAttribute(k_attn,
            cudaFuncAttributeMaxDynamicSharedMemorySize, sm_att);
        cfg_done = 1;
    }

    const dim3 g_qkv(C_ / 128, NT / 128, 3);   // 8 x 64 x 3
    const dim3 g_c(C_ / 128, NT / 128, 1);     // 8 x 64
    const dim3 g_att(T_ / 256, B_ * H_);       // 8 x 64

    __half* pXh; cudaGetSymbolAddress((void**)&pXh, g_xh);
    __half* pP;  cudaGetSymbolAddress((void**)&pP,  g_P);
    __half* pP2; cudaGetSymbolAddress((void**)&pP2, g_P2);
    __half* pWu; cudaGetSymbolAddress((void**)&pWu, g_Wu);

    k_prep<<<2560, 256>>>(x, qU, kU, vU, cU, qV, kV, vV, cV);      // 1
    k_g1a<<<NT / 32, 128, sm_g1a>>>(pXh, pP);                      // 2
    k_g2<<<g_qkv, 256, sm_g2>>>(pP, 192, pWu, 0, nullptr);         // 3
    k_attn<<<g_att, 256, sm_att>>>();                              // 4
    k_g1b<<<NT / 64, 256, sm_g1b>>>(pP2);                          // 5
    k_g2<<<g_c, 256, sm_g2>>>(pP2, 64, pWu + 3 * 65536, 1, out);   // 6
}

// round 16
// speedup vs baseline: 1.1443x; 1.1443x over previous
#include <cuda_runtime.h>
#include <cuda_fp16.h>
#include <cstdint>
#include <math.h>

#define B_ 4
#define T_ 2048
#define C_ 1024
#define H_ 16
#define D_ 64
#define R_ 64
#define NT 8192   // B*T

// ---------------- scratch (device globals; no allocation) ----------------
__device__ __half g_xh[NT * C_];      // x converted to half
__device__ __half g_W[256 * 1024];    // stacked scaled V-weights (half)
__device__ __half g_Wu[4 * 1024 * 64];// U weights (half)
__device__ __half g_P[NT * 192];      // rank-space P for q,k,v
__device__ __half g_P2[NT * 64];      // rank-space P for c-proj
__device__ __half g_Qh[NT * C_];      // [B,T,C] flat, pre-scaled by 0.125*log2e
__device__ __half g_Kh[NT * C_];      // [B,T,C] flat
__device__ __half g_Vh[NT * C_];      // [B,T,C] flat
__device__ __half g_Yh[NT * C_];      // attention out [B,T,C]

// =================== portable tensor-core helpers (sm_80+) =================
__device__ __forceinline__ void mma_f16(float* d, const uint32_t* a,
                                        uint32_t b0, uint32_t b1) {
    asm volatile(
        "mma.sync.aligned.m16n8k16.row.col.f32.f16.f16.f32 "
        "{%0,%1,%2,%3}, {%4,%5,%6,%7}, {%8,%9}, {%0,%1,%2,%3};"
        : "+f"(d[0]), "+f"(d[1]), "+f"(d[2]), "+f"(d[3])
        : "r"(a[0]), "r"(a[1]), "r"(a[2]), "r"(a[3]), "r"(b0), "r"(b1));
}
__device__ __forceinline__ uint32_t smem_u32(const void* p) {
    uint32_t a;
    asm("{ .reg .u64 t; cvta.to.shared.u64 t, %1; cvt.u32.u64 %0, t; }"
        : "=r"(a) : "l"(p));
    return a;
}
__device__ __forceinline__ void cp16(uint32_t dst, const void* src) {
    asm volatile("cp.async.cg.shared.global [%0], [%1], 16;"
                 :: "r"(dst), "l"(src));
}
#define CP_COMMIT() asm volatile("cp.async.commit_group;" ::: "memory")
#define CP_WAIT(n)  asm volatile("cp.async.wait_group %0;" :: "n"(n) : "memory")
#define LDSM4(r, a)                                                         \
    asm volatile("ldmatrix.sync.aligned.m8n8.x4.shared.b16 "                \
                 "{%0,%1,%2,%3}, [%4];"                                     \
                 : "=r"((r)[0]), "=r"((r)[1]), "=r"((r)[2]), "=r"((r)[3])   \
                 : "r"(a))
#define LDSM4T(r, a)                                                        \
    asm volatile("ldmatrix.sync.aligned.m8n8.x4.trans.shared.b16 "          \
                 "{%0,%1,%2,%3}, [%4];"                                     \
                 : "=r"((r)[0]), "=r"((r)[1]), "=r"((r)[2]), "=r"((r)[3])   \
                 : "r"(a))
__device__ __forceinline__ uint32_t pack_h2(float lo, float hi) {
    __half2 h = __floats2half2_rn(lo, hi);
    return *(uint32_t*)&h;
}
__device__ __forceinline__ uint32_t h2exp2(uint32_t u) {
    uint32_t r;
    asm("ex2.approx.f16x2 %0, %1;" : "=r"(r) : "r"(u));
    return r;
}

// ---------------------------------------------------------------------------
// K_prep: blocks [0,2048): x fp32 -> half (wide uint4 stores)
//         blocks [2048,2304): scaled V-weights -> g_W
//         blocks [2304,2560): U weights -> g_Wu
// ---------------------------------------------------------------------------
__global__ __launch_bounds__(256) void k_prep(
    const float* __restrict__ x,
    const float* __restrict__ qU, const float* __restrict__ kU,
    const float* __restrict__ vU, const float* __restrict__ cU,
    const float* __restrict__ qV, const float* __restrict__ kV,
    const float* __restrict__ vV, const float* __restrict__ cV) {
    const int b = blockIdx.x, tid = threadIdx.x;
    if (b < 2048) {
        const int base = (b * 256 + tid) * 16;
        uint32_t o[8];
        #pragma unroll
        for (int g = 0; g < 4; g++) {
            float4 v = *(const float4*)(x + base + g * 4);
            o[2 * g]     = pack_h2(v.x, v.y);
            o[2 * g + 1] = pack_h2(v.z, v.w);
        }
        *(uint4*)(g_xh + base)     = make_uint4(o[0], o[1], o[2], o[3]);
        *(uint4*)(g_xh + base + 8) = make_uint4(o[4], o[5], o[6], o[7]);
    } else if (b < 2304) {
        const int bb = b - 2048;
        const int grp = bb >> 6, r = bb & 63;
        const float* Vsrc = (grp == 0) ? qV : (grp == 1) ? kV
                          : (grp == 2) ? vV : cV;
        float sc = powf((float)(r + 1), -0.7f);
        if (grp == 0) sc *= 0.125f * 1.4426950408889634f;
        const int c = tid * 4;
        float4 v = *(const float4*)(Vsrc + (size_t)r * 1024 + c);
        *(__half2*)(g_W + (size_t)bb * 1024 + c)     = __floats2half2_rn(v.x * sc, v.y * sc);
        *(__half2*)(g_W + (size_t)bb * 1024 + c + 2) = __floats2half2_rn(v.z * sc, v.w * sc);
    } else {
        const float* Us[4] = {qU, kU, vU, cU};
        const int base = (b - 2304) * 1024 + tid * 4;
        const int w = base >> 16, off = base & 65535;
        float4 u = *(const float4*)(Us[w] + off);
        *(__half2*)(g_Wu + base)     = __floats2half2_rn(u.x, u.y);
        *(__half2*)(g_Wu + base + 2) = __floats2half2_rn(u.z, u.w);
    }
}

// ---------------------------------------------------------------------------
// K1a: stage-1 qkv GEMM  P[m, n] = x[m,:1024] @ W[n,:1024]^T, NOUT=192.
// 128 threads/CTA, tile 32x192, grid 256. 3-stage cp.async, 1 sync/chunk.
// ---------------------------------------------------------------------------
#define PADH1 40   // halfs; 80B row stride
__global__ __launch_bounds__(128) void k_g1a(const __half* __restrict__ A,
                                             __half* __restrict__ Pout) {
    extern __shared__ __half sg1h[];
    const int tid = threadIdx.x, w = tid >> 5, lane = tid & 31;
    const int quad = lane >> 2, qc = lane & 3;
    const int m0 = blockIdx.x * 32;
    constexpr int STRIDE = (32 + 192) * PADH1;
    const uint32_t sb = smem_u32(sg1h);

    auto stage = [&](int ch, int s) {
        const int k0 = ch * 32;
        const uint32_t base = sb + s * STRIDE * 2;
        #pragma unroll
        for (int i = tid; i < (32 + 192) * 4; i += 128) {
            int row = i >> 2, c8 = (i & 3) * 8;
            const __half* src = (row < 32)
                ? A   + (size_t)(m0 + row) * 1024 + k0 + c8
                : g_W + (size_t)(row - 32) * 1024 + k0 + c8;
            cp16(base + (row * PADH1 + c8) * 2, src);
        }
    };

    float acc[2][6][4];
    #pragma unroll
    for (int mf = 0; mf < 2; mf++)
        #pragma unroll
        for (int nb = 0; nb < 6; nb++)
            #pragma unroll
            for (int i = 0; i < 4; i++) acc[mf][nb][i] = 0.f;

    stage(0, 0); CP_COMMIT();
    stage(1, 1); CP_COMMIT();

    for (int ch = 0; ch < 32; ch++) {
        CP_WAIT(1);
        __syncthreads();
        if (ch + 2 < 32) stage(ch + 2, (ch + 2) % 3);
        CP_COMMIT();                      // unconditional (may be empty)
        const __half* Ab = sg1h + (ch % 3) * STRIDE;
        const __half* Bb = Ab + 32 * PADH1;
        #pragma unroll
        for (int kb = 0; kb < 2; kb++) {
            uint32_t a[2][4];
            #pragma unroll
            for (int mf = 0; mf < 2; mf++) {
                const __half* ap = Ab + (mf * 16 + quad) * PADH1
                                 + kb * 16 + 2 * qc;
                a[mf][0] = *(const uint32_t*)(ap);
                a[mf][1] = *(const uint32_t*)(ap + 8 * PADH1);
                a[mf][2] = *(const uint32_t*)(ap + 8);
                a[mf][3] = *(const uint32_t*)(ap + 8 * PADH1 + 8);
            }
            #pragma unroll
            for (int nb = 0; nb < 6; nb++) {
                const __half* bp = Bb + (w * 48 + nb * 8 + quad) * PADH1
                                 + kb * 16 + 2 * qc;
                uint32_t b0 = *(const uint32_t*)(bp);
                uint32_t b1 = *(const uint32_t*)(bp + 8);
                mma_f16(acc[0][nb], a[0], b0, b1);
                mma_f16(acc[1][nb], a[1], b0, b1);
            }
        }
    }

    #pragma unroll
    for (int mf = 0; mf < 2; mf++) {
        const int row = m0 + mf * 16 + quad;
        #pragma unroll
        for (int nb = 0; nb < 6; nb++) {
            const int col = w * 48 + nb * 8 + 2 * qc;
            *(__half2*)(Pout + (size_t)row * 192 + col) =
                __floats2half2_rn(acc[mf][nb][0], acc[mf][nb][1]);
            *(__half2*)(Pout + (size_t)(row + 8) * 192 + col) =
                __floats2half2_rn(acc[mf][nb][2], acc[mf][nb][3]);
        }
    }
}

// ---------------------------------------------------------------------------
// K1b: stage-1 c-proj GEMM  P2[m,n] = Y[m,:1024] @ W[192+n,:1024]^T, NOUT=64
// 256 threads, tile 64x64, 3-stage cp.async, single sync per chunk.
// ---------------------------------------------------------------------------
__global__ __launch_bounds__(256) void k_g1b(__half* __restrict__ Pout) {
    extern __shared__ __half sg1bh[];
    const int tid = threadIdx.x, w = tid >> 5, lane = tid & 31;
    const int quad = lane >> 2, qc = lane & 3;
    const int wm = w & 1, wn = w >> 1;
    const int m0 = blockIdx.x * 64;
    constexpr int STRIDE = 128 * PADH1;
    const __half* Wp = g_W + (size_t)192 * 1024;
    const uint32_t sb = smem_u32(sg1bh);

    auto stage = [&](int ch, int s) {
        const int k0 = ch * 32;
        const uint32_t base = sb + s * STRIDE * 2;
        #pragma unroll
        for (int i = tid; i < 128 * 4; i += 256) {
            int row = i >> 2, c8 = (i & 3) * 8;
            const __half* src = (row < 64)
                ? g_Yh + (size_t)(m0 + row) * 1024 + k0 + c8
                : Wp   + (size_t)(row - 64) * 1024 + k0 + c8;
            cp16(base + (row * PADH1 + c8) * 2, src);
        }
    };

    float acc[2][2][4] = {};
    stage(0, 0); CP_COMMIT();
    stage(1, 1); CP_COMMIT();

    for (int ch = 0; ch < 32; ch++) {
        CP_WAIT(1);
        __syncthreads();
        if (ch + 2 < 32) stage(ch + 2, (ch + 2) % 3);
        CP_COMMIT();                      // unconditional (may be empty)
        const __half* Ab = sg1bh + (ch % 3) * STRIDE;
        const __half* Bb = Ab + 64 * PADH1;
        #pragma unroll
        for (int kb = 0; kb < 2; kb++) {
            uint32_t a[2][4];
            #pragma unroll
            for (int mf = 0; mf < 2; mf++) {
                const __half* ap = Ab + (wm * 32 + mf * 16 + quad) * PADH1
                                 + kb * 16 + 2 * qc;
                a[mf][0] = *(const uint32_t*)(ap);
                a[mf][1] = *(const uint32_t*)(ap + 8 * PADH1);
                a[mf][2] = *(const uint32_t*)(ap + 8);
                a[mf][3] = *(const uint32_t*)(ap + 8 * PADH1 + 8);
            }
            #pragma unroll
            for (int nb = 0; nb < 2; nb++) {
                const __half* bp = Bb + (wn * 16 + nb * 8 + quad) * PADH1
                                 + kb * 16 + 2 * qc;
                uint32_t b0 = *(const uint32_t*)(bp);
                uint32_t b1 = *(const uint32_t*)(bp + 8);
                mma_f16(acc[0][nb], a[0], b0, b1);
                mma_f16(acc[1][nb], a[1], b0, b1);
            }
        }
    }

    #pragma unroll
    for (int mf = 0; mf < 2; mf++) {
        const int row = m0 + wm * 32 + mf * 16 + quad;
        #pragma unroll
        for (int nb = 0; nb < 2; nb++) {
            const int col = wn * 16 + nb * 8 + 2 * qc;
            *(__half2*)(Pout + (size_t)row * 64 + col) =
                __floats2half2_rn(acc[mf][nb][0], acc[mf][nb][1]);
            *(__half2*)(Pout + (size_t)(row + 8) * 64 + col) =
                __floats2half2_rn(acc[mf][nb][2], acc[mf][nb][3]);
        }
    }
}

// ---------------------------------------------------------------------------
// K2: stage-2 GEMM  y[m,n] = P[m,:64] @ U[n0+n,:64]^T   (non-persistent)
// M-tile 128, N-tile 128, K=64 single shot.
// mode 0: SMEM-transposed epilogue -> coalesced 16B stores into flat
// [B,T,C] Q/K/V (z selects dst).  mode 1: fp32 out, direct stores.
// ---------------------------------------------------------------------------
#define PADH2 72   // halfs; 144B row stride
#define PADT  136  // halfs; transpose buffer stride
__global__ __launch_bounds__(256) void k_g2(const __half* __restrict__ Pbase,
                                            int ps,
                                            const __half* __restrict__ Wubase,
                                            int mode, float* __restrict__ outp) {
    extern __shared__ __half sg2h[];
    __half* As = sg2h;                 // [128][PADH2]
    __half* Bs = sg2h + 128 * PADH2;   // [128][PADH2]
    const int tid = threadIdx.x, w = tid >> 5, lane = tid & 31;
    const int quad = lane >> 2, qc = lane & 3;
    const int m0 = blockIdx.y * 128, n0 = blockIdx.x * 128;
    const int z = blockIdx.z;
    const __half* Pin = Pbase + (mode == 0 ? z * 64 : 0);
    const __half* Wu  = Wubase + (mode == 0 ? z * 65536 : 0);
    const uint32_t sb = smem_u32(sg2h);

    #pragma unroll
    for (int t = 0; t < 4; t++) {       // A: 1024 cp16
        int idx = tid + t * 256;
        int r = idx >> 3, c8 = (idx & 7) * 8;
        cp16(sb + (r * PADH2 + c8) * 2, Pin + (size_t)(m0 + r) * ps + c8);
    }
    #pragma unroll
    for (int t = 0; t < 4; t++) {       // B: 1024 cp16
        int idx = tid + t * 256;
        int n = idx >> 3, c8 = (idx & 7) * 8;
        cp16(sb + (128 * PADH2 + n * PADH2 + c8) * 2,
             Wu + (size_t)(n0 + n) * 64 + c8);
    }
    CP_COMMIT();
    CP_WAIT(0);
    __syncthreads();

    float acc[16][4];
    #pragma unroll
    for (int nb = 0; nb < 16; nb++)
        #pragma unroll
        for (int i = 0; i < 4; i++) acc[nb][i] = 0.f;

    #pragma unroll
    for (int kb = 0; kb < 4; kb++) {
        uint32_t a[4];
        const __half* ap = As + (w * 16 + quad) * PADH2 + kb * 16 + 2 * qc;
        a[0] = *(const uint32_t*)(ap);
        a[1] = *(const uint32_t*)(ap + 8 * PADH2);
        a[2] = *(const uint32_t*)(ap + 8);
        a[3] = *(const uint32_t*)(ap + 8 * PADH2 + 8);
        #pragma unroll
        for (int nb = 0; nb < 16; nb++) {
            const __half* bp = Bs + (nb * 8 + quad) * PADH2 + kb * 16 + 2 * qc;
            mma_f16(acc[nb], a, *(const uint32_t*)(bp),
                    *(const uint32_t*)(bp + 8));
        }
    }

    if (mode == 0) {
        __syncthreads();               // done reading As/Bs as inputs
        __half* Ts = sg2h;             // reuse as [128][PADT] transpose buffer
        const int r0 = w * 16 + quad;
        #pragma unroll
        for (int nb = 0; nb < 16; nb++) {
            const int colh = nb * 8 + 2 * qc;
            *(__half2*)(Ts + r0 * PADT + colh) =
                __floats2half2_rn(acc[nb][0], acc[nb][1]);
            *(__half2*)(Ts + (r0 + 8) * PADT + colh) =
                __floats2half2_rn(acc[nb][2], acc[nb][3]);
        }
        __syncthreads();
        __half* dst = (z == 0) ? g_Qh : (z == 1) ? g_Kh : g_Vh;
        #pragma unroll
        for (int t = 0; t < 8; t++) {  // 128 rows x 16 chunks, coalesced 16B
            int idx = tid + t * 256;
            int row = idx >> 4, ch = idx & 15;
            *(uint4*)(dst + (size_t)(m0 + row) * C_ + n0 + ch * 8) =
                *(const uint4*)(Ts + row * PADT + ch * 8);
        }
    } else {
        const int row = m0 + w * 16 + quad;
        #pragma unroll
        for (int nb = 0; nb < 16; nb++) {
            const int col = n0 + nb * 8 + 2 * qc;
            float* p0 = outp + (size_t)row * C_ + col;
            *(float2*)p0 = make_float2(acc[nb][0], acc[nb][1]);
            *(float2*)(p0 + 8 * C_) = make_float2(acc[nb][2], acc[nb][3]);
        }
    }
}

// ---------------------------------------------------------------------------
// K3: causal flash attention (R13 algorithm; Q/K/V now flat [B,T,C], so
// rows are strided by C_ and the head selects a 64-col slice).
// 128 q-rows/CTA, 8 warps x 16 rows, pair-processed 64-key tiles,
// 4-deep buffers, one __syncthreads per pair, reg-addressed LDSM.
// exp via ex2.approx.f16x2; row-sums via constant ones b-fragment.
// ---------------------------------------------------------------------------
#define PADA 72                   // halfs; 144B stride
#define KVB2 (64 * PADA * 2)      // bytes per single K or V tile buffer
__global__ __launch_bounds__(256, 2) void k_attn() {
    extern __shared__ __half sah[];
    const int tid = threadIdx.x, w = tid >> 5, lane = tid & 31;
    const int quad = lane >> 2, qc = lane & 3;
    const int msel = lane >> 3, rsel = lane & 7;
    const int mrow_a = (msel & 1) * 8 + rsel;   // Q / V(trans) row part
    const int mcol_a = (msel >> 1) * 8;
    const int mrow_b = (msel >> 1) * 8 + rsel;  // K row part
    const int mcol_b = (msel & 1) * 8;
    const int bh = blockIdx.y;
    const int b = bh >> 4, h = bh & 15;
    const int qt = gridDim.x - 1 - blockIdx.x;  // heavy tiles first
    const int q0 = qt * 128;
    const __half* Qb = g_Qh + (size_t)b * T_ * C_ + h * 64;
    const __half* Kb = g_Kh + (size_t)b * T_ * C_ + h * 64;
    const __half* Vb = g_Vh + (size_t)b * T_ * C_ + h * 64;
    const int npair = qt + 1;                   // nt = 2qt+2 tiles, paired
    const uint32_t vones = (quad == 0) ? 0x3C003C00u : 0u;  // half2 (1,1)

    // ---- precomputed SMEM addresses (bytes) ----
    const uint32_t SB = smem_u32(sah);
    const uint32_t QS = SB;                     // Qs [128][PADA]
    const uint32_t KS = SB + 128 * PADA * 2;    // Ksb[4][64][PADA]
    const uint32_t VS = KS + 4 * KVB2;          // Vsb[4][64][PADA]
    const uint32_t ka0 = KS + (mrow_b * PADA + mcol_b) * 2;
    const uint32_t va0 = VS + (mrow_a * PADA + mcol_a) * 2;
    // staging: thread covers rows r and r+32 at col c8 (row stride C_)
    const int r = tid >> 3, c8 = (tid & 7) * 8;
    const size_t gs0 = (size_t)r * C_ + c8, gs1 = gs0 + (size_t)32 * C_;
    const uint32_t kst0 = KS + (r * PADA + c8) * 2;
    const uint32_t kst1 = kst0 + 32 * PADA * 2;
    const uint32_t vst0 = VS + (r * PADA + c8) * 2;
    const uint32_t vst1 = vst0 + 32 * PADA * 2;

    auto stage = [&](int j) {
        const __half* Kt = Kb + (size_t)j * 64 * C_;
        const __half* Vt = Vb + (size_t)j * 64 * C_;
        const uint32_t bo = (j & 3) * KVB2;
        cp16(kst0 + bo, Kt + gs0);
        cp16(kst1 + bo, Kt + gs1);
        cp16(vst0 + bo, Vt + gs0);
        cp16(vst1 + bo, Vt + gs1);
    };

    // Q tile (128 rows) + first pair, one commit group
    #pragma unroll
    for (int t = 0; t < 4; t++) {
        const int row = r + t * 32;
        cp16(QS + (row * PADA + c8) * 2,
             Qb + (size_t)(q0 + row) * C_ + c8);
    }
    stage(0);
    stage(1);
    CP_COMMIT();

    uint32_t qa[4][4];
    float o[8][4] = {};
    float oS[4] = {};       // ones-frag accumulator: n=0 col = Sum(p)

    auto compute = [&](int j, bool maskt) {
        const uint32_t kbase = ka0 + (j & 3) * KVB2;
        const uint32_t vbase = va0 + (j & 3) * KVB2;

        // S = Q @ K^T : 16x64 per warp
        float s[8][4];
        #pragma unroll
        for (int nb = 0; nb < 8; nb++)
            #pragma unroll
            for (int i = 0; i < 4; i++) s[nb][i] = 0.f;
        #pragma unroll
        for (int kb = 0; kb < 4; kb++)
            #pragma unroll
            for (int nbp = 0; nbp < 4; nbp++) {
                uint32_t bf[4];
                LDSM4(bf, kbase + (nbp * 16 * PADA + kb * 16) * 2);
                mma_f16(s[2 * nbp],     qa[kb], bf[0], bf[1]);
                mma_f16(s[2 * nbp + 1], qa[kb], bf[2], bf[3]);
            }

        // causal mask (final pair only; literal bool -> DCE in hot path)
        if (maskt) {
            const int rowrel0 = q0 + w * 16 + quad - 64 * j;
            #pragma unroll
            for (int nb = 0; nb < 8; nb++) {
                const int k0 = nb * 8 + 2 * qc;
                if (k0 > rowrel0)         s[nb][0] = -1e30f;
                if (k0 + 1 > rowrel0)     s[nb][1] = -1e30f;
                if (k0 > rowrel0 + 8)     s[nb][2] = -1e30f;
                if (k0 + 1 > rowrel0 + 8) s[nb][3] = -1e30f;
            }
        }

        // P = 2^S in f16x2; O += P @ V; Sum(p) += P @ ones
        #pragma unroll
        for (int kb = 0; kb < 4; kb++) {
            uint32_t pa[4];
            pa[0] = h2exp2(pack_h2(s[2 * kb][0],     s[2 * kb][1]));
            pa[1] = h2exp2(pack_h2(s[2 * kb][2],     s[2 * kb][3]));
            pa[2] = h2exp2(pack_h2(s[2 * kb + 1][0], s[2 * kb + 1][1]));
            pa[3] = h2exp2(pack_h2(s[2 * kb + 1][2], s[2 * kb + 1][3]));
            #pragma unroll
            for (int nbp = 0; nbp < 4; nbp++) {
                uint32_t vf[4];
                LDSM4T(vf, vbase + (kb * 16 * PADA + nbp * 16) * 2);
                mma_f16(o[2 * nbp],     pa, vf[0], vf[1]);
                mma_f16(o[2 * nbp + 1], pa, vf[2], vf[3]);
            }
            mma_f16(oS, pa, vones, vones);   // constant ones b-frag
        }
    };

    for (int p = 0; p < npair; p++) {
        CP_WAIT(0);
        __syncthreads();
        if (p == 0) {        // Q a-frags once (Q arrived with first group)
            #pragma unroll
            for (int kb = 0; kb < 4; kb++)
                LDSM4(qa[kb],
                      QS + ((w * 16 + mrow_a) * PADA + kb * 16 + mcol_a) * 2);
        }
        if (p + 1 < npair) {
            stage(2 * p + 2);
            stage(2 * p + 3);
            CP_COMMIT();
            compute(2 * p,     false);
            compute(2 * p + 1, false);
        } else {             // final pair carries the causal mask
            compute(2 * p,     true);
            compute(2 * p + 1, true);
        }
    }

    // ---- epilogue: Sum(p) at n=0 of oS frag (qc==0 lanes) ----
    const float l0 = __shfl_sync(0xffffffffu, oS[0], lane & 28);
    const float l1 = __shfl_sync(0xffffffffu, oS[2], lane & 28);
    const float inv0 = 1.f / l0, inv1 = 1.f / l1;
    const int r0 = q0 + w * 16 + quad;
    __half* y0 = g_Yh + ((size_t)b * T_ + r0) * C_ + h * 64;
    __half* y1 = y0 + 8 * C_;
    #pragma unroll
    for (int nb = 0; nb < 8; nb++) {
        const int c = nb * 8 + 2 * qc;
        *(__half2*)(y0 + c) = __floats2half2_rn(o[nb][0] * inv0,
                                                o[nb][1] * inv0);
        *(__half2*)(y1 + c) = __floats2half2_rn(o[nb][2] * inv1,
                                                o[nb][3] * inv1);
    }
}

// ---------------------------------------------------------------------------
extern "C" void kernel_launch(void* const* d_in, const int* in_sizes, int n_in,
                              void* d_out, int out_size) {
    (void)in_sizes; (void)n_in; (void)out_size;
    const float* x  = (const float*)d_in[0];
    const float* qU = (const float*)d_in[1];
    const float* qV = (const float*)d_in[2];
    const float* kU = (const float*)d_in[3];
    const float* kV = (const float*)d_in[4];
    const float* vU = (const float*)d_in[5];
    const float* vV = (const float*)d_in[6];
    const float* cU = (const float*)d_in[7];
    const float* cV = (const float*)d_in[8];
    float* out = (float*)d_out;

    const int sm_g1a = 3 * (32 + 192) * PADH1 * 2;              // 53760
    const int sm_g1b = 3 * 128 * PADH1 * 2;                     // 30720
    const int sm_g2  = 2 * 128 * PADH2 * 2;                     // 36864
    const int sm_att = (128 * PADA + 8 * 64 * PADA) * 2;        // 92160
    static int cfg_done = 0;
    if (!cfg_done) {
        cudaFuncSetAttribute(k_g1a,
            cudaFuncAttributeMaxDynamicSharedMemorySize, sm_g1a);
        cudaFuncSetAttribute(k_g1b,
            cudaFuncAttributeMaxDynamicSharedMemorySize, sm_g1b);
        cudaFuncSetAttribute(k_g2,
            cudaFuncAttributeMaxDynamicSharedMemorySize, sm_g2);
        cudaFuncSetAttribute(k_attn,
            cudaFuncAttributeMaxDynamicSharedMemorySize, sm_att);
        cfg_done = 1;
    }

    const dim3 g_qkv(C_ / 128, NT / 128, 3);   // 8 x 64 x 3
    const dim3 g_c(C_ / 128, NT / 128, 1);     // 8 x 64
    const dim3 g_att(T_ / 128, B_ * H_);       // 16 x 64

    __half* pXh; cudaGetSymbolAddress((void**)&pXh, g_xh);
    __half* pP;  cudaGetSymbolAddress((void**)&pP,  g_P);
    __half* pP2; cudaGetSymbolAddress((void**)&pP2, g_P2);
    __half* pWu; cudaGetSymbolAddress((void**)&pWu, g_Wu);

    k_prep<<<2560, 256>>>(x, qU, kU, vU, cU, qV, kV, vV, cV);      // 1
    k_g1a<<<NT / 32, 128, sm_g1a>>>(pXh, pP);                      // 2
    k_g2<<<g_qkv, 256, sm_g2>>>(pP, 192, pWu, 0, nullptr);         // 3
    k_attn<<<g_att, 256, sm_att>>>();                              // 4
    k_g1b<<<NT / 64, 256, sm_g1b>>>(pP2);                          // 5
    k_g2<<<g_c, 256, sm_g2>>>(pP2, 64, pWu + 3 * 65536, 1, out);   // 6
}